// round 2
// baseline (speedup 1.0000x reference)
#include <cuda_runtime.h>
#include <math.h>

#define NB 256
#define NR 1152
#define NC2 10
#define NO 16
#define NI 8

// ------------- scratch (device globals) -------------
__device__ float g_pool1[(size_t)NB * 64 * 38 * 38];
__device__ float g_conv2o[(size_t)NB * 128 * 38 * 38];
__device__ float g_pool2[(size_t)NB * 128 * 20 * 20];
__device__ float g_wT[10368 * 256];
__device__ float g_uraw[(size_t)NB * 9216];
__device__ float g_u[(size_t)NB * 9216];
__device__ float g_uhat[(size_t)NB * NR * NC2 * NO];
__device__ float g_bij[NR * NC2];
__device__ float g_cij[NR * NC2];
__device__ float g_v[NB * NC2 * NO];

// ------------- zero b_ij -------------
__global__ void k_zero() {
    int i = blockIdx.x * blockDim.x + threadIdx.x;
    if (i < NR * NC2) g_bij[i] = 0.f;
}

// ------------- conv1(3->64,3x3,valid)+ReLU+maxpool(2,2,pad1) -------------
__global__ void __launch_bounds__(256) k_conv1pool(const float* __restrict__ data,
                                                   const float* __restrict__ w1,
                                                   const float* __restrict__ b1) {
    int idx = blockIdx.x * blockDim.x + threadIdx.x;   // 1444 blocks * 256 = B*1444
    int p = idx % 1444;
    int b = idx / 1444;
    int pj = p / 38, pi = p % 38;
    int y0 = 2 * pj - 1, x0 = 2 * pi - 1;

    float iv[3][4][4];
#pragma unroll
    for (int ic = 0; ic < 3; ic++)
#pragma unroll
        for (int dy = 0; dy < 4; dy++) {
            int yy = y0 + dy;
#pragma unroll
            for (int dx = 0; dx < 4; dx++) {
                int xx = x0 + dx;
                float v = 0.f;
                if (yy >= 0 && yy < 76 && xx >= 0 && xx < 76)
                    v = data[((size_t)(b * 3 + ic) * 76 + yy) * 76 + xx];
                iv[ic][dy][dx] = v;
            }
        }

    bool rv0 = (y0 >= 0), rv1 = (y0 + 1 <= 73);
    bool cv0 = (x0 >= 0), cv1 = (x0 + 1 <= 73);
    size_t obase = (size_t)b * 64 * 1444 + (size_t)pj * 38 + pi;

#pragma unroll 1
    for (int oc = 0; oc < 64; oc++) {
        const float* wp = w1 + oc * 27;
        float s00 = 0.f, s01 = 0.f, s10 = 0.f, s11 = 0.f;
#pragma unroll
        for (int k = 0; k < 27; k++) {
            int ic = k / 9, r = (k / 3) % 3, c2 = k % 3;
            float w = __ldg(wp + k);
            s00 = fmaf(iv[ic][r][c2],         w, s00);
            s01 = fmaf(iv[ic][r][c2 + 1],     w, s01);
            s10 = fmaf(iv[ic][r + 1][c2],     w, s10);
            s11 = fmaf(iv[ic][r + 1][c2 + 1], w, s11);
        }
        float bo = __ldg(b1 + oc);
        float m = 0.f;
        if (rv0 && cv0) m = fmaxf(m, s00 + bo);
        if (rv0 && cv1) m = fmaxf(m, s01 + bo);
        if (rv1 && cv0) m = fmaxf(m, s10 + bo);
        if (rv1 && cv1) m = fmaxf(m, s11 + bo);
        g_pool1[obase + (size_t)oc * 1444] = m;
    }
}

// ------------- conv2(64->128,3x3,pad1)+ReLU -------------
// block (64,4): tx=oc-half, ty=row-in-strip of 4. 8-ic tiles in smem.
__global__ void __launch_bounds__(256) k_conv2(const float* __restrict__ w2,
                                               const float* __restrict__ b2) {
    __shared__ float s_in[8 * 6 * 40];     // 1920
    __shared__ float s_w[72 * 128];        // 9216

    int b = blockIdx.y;
    int r0 = blockIdx.x * 4;
    int tx = threadIdx.x;
    int ty = threadIdx.y;
    int tid = ty * 64 + tx;
    int row = r0 + ty;

    float acc0[38], acc1[38];
#pragma unroll
    for (int x = 0; x < 38; x++) { acc0[x] = 0.f; acc1[x] = 0.f; }

#pragma unroll 1
    for (int ic0 = 0; ic0 < 64; ic0 += 8) {
        __syncthreads();
        for (int i = tid; i < 1920; i += 256) {
            int ic = i / 240, rem = i % 240;
            int rr = rem / 40, cc = rem % 40;
            int gr = r0 - 1 + rr, gc = cc - 1;
            float vv = 0.f;
            if (gr >= 0 && gr < 38 && gc >= 0 && gc < 38)
                vv = g_pool1[(((size_t)b * 64 + ic0 + ic) * 38 + gr) * 38 + gc];
            s_in[i] = vv;
        }
        for (int i = tid; i < 9216; i += 256) {
            int k = i / 128, oc = i % 128;
            s_w[i] = w2[(size_t)oc * 576 + ic0 * 9 + k];
        }
        __syncthreads();

        if (row < 38) {
#pragma unroll 1
            for (int icl = 0; icl < 8; icl++) {
#pragma unroll
                for (int ky = 0; ky < 3; ky++) {
                    const float* irow = s_in + icl * 240 + (ty + ky) * 40;
                    const float* wr = s_w + (icl * 9 + ky * 3) * 128;
                    float wA0 = wr[tx],       wB0 = wr[tx + 64];
                    float wA1 = wr[128 + tx], wB1 = wr[128 + tx + 64];
                    float wA2 = wr[256 + tx], wB2 = wr[256 + tx + 64];
                    float v0 = irow[0], v1 = irow[1];
#pragma unroll
                    for (int x = 0; x < 38; x++) {
                        float v2 = irow[x + 2];
                        acc0[x] = fmaf(v2, wA2, fmaf(v1, wA1, fmaf(v0, wA0, acc0[x])));
                        acc1[x] = fmaf(v2, wB2, fmaf(v1, wB1, fmaf(v0, wB0, acc1[x])));
                        v0 = v1; v1 = v2;
                    }
                }
            }
        }
    }

    if (row < 38) {
        float bA = __ldg(b2 + tx), bB = __ldg(b2 + tx + 64);
        size_t baseA = (((size_t)b * 128 + tx) * 38 + row) * 38;
        size_t baseB = (((size_t)b * 128 + tx + 64) * 38 + row) * 38;
#pragma unroll
        for (int x = 0; x < 38; x++) {
            g_conv2o[baseA + x] = fmaxf(acc0[x] + bA, 0.f);
            g_conv2o[baseB + x] = fmaxf(acc1[x] + bB, 0.f);
        }
    }
}

// ------------- maxpool 38->20 (pad1) -------------
__global__ void k_pool2() {
    int idx = blockIdx.x * blockDim.x + threadIdx.x;   // B*128*400
    int pi = idx % 20;
    int pj = (idx / 20) % 20;
    int ch = idx / 400;
    const float* base = g_conv2o + (size_t)ch * 1444;
    int y0 = 2 * pj - 1, x0 = 2 * pi - 1;
    float m = 0.f;   // inputs relu'd >= 0
#pragma unroll
    for (int dy = 0; dy < 2; dy++) {
        int y = y0 + dy;
        if (y < 0 || y > 37) continue;
#pragma unroll
        for (int dx = 0; dx < 2; dx++) {
            int x = x0 + dx;
            if (x < 0 || x > 37) continue;
            m = fmaxf(m, base[y * 38 + x]);
        }
    }
    g_pool2[idx] = m;
}

// ------------- transpose prim weights [oc][k] -> [k][oc] -------------
__global__ void k_wT(const float* __restrict__ pw) {
    int i = blockIdx.x * blockDim.x + threadIdx.x;     // 10368*256
    int k = i / 256, oc = i % 256;
    g_wT[i] = pw[(size_t)oc * 10368 + k];
}

// ------------- PrimaryCaps conv (128->256, 9x9, s2, 6x6 out) -------------
__global__ void __launch_bounds__(256) k_prim(const float* __restrict__ pb) {
    __shared__ float s_in[16 * 400];   // 25.6 KB
    int b = blockIdx.x;
    int oc = threadIdx.x;

    float acc[36];
#pragma unroll
    for (int s = 0; s < 36; s++) acc[s] = 0.f;

#pragma unroll 1
    for (int ic0 = 0; ic0 < 128; ic0 += 16) {
        __syncthreads();
        for (int i = oc; i < 6400; i += 256)
            s_in[i] = g_pool2[((size_t)b * 128 + ic0) * 400 + i];
        __syncthreads();

#pragma unroll 1
        for (int icl = 0; icl < 16; icl++) {
#pragma unroll 1
            for (int ky = 0; ky < 9; ky++) {
                float w[9];
                const float* wp = g_wT + ((size_t)(ic0 + icl) * 81 + ky * 9) * 256 + oc;
#pragma unroll
                for (int kx = 0; kx < 9; kx++) w[kx] = wp[kx * 256];
#pragma unroll
                for (int sj = 0; sj < 6; sj++) {
                    const float* row = s_in + icl * 400 + (2 * sj + ky) * 20;
                    float rv[19];
#pragma unroll
                    for (int x = 0; x < 19; x++) rv[x] = row[x];
#pragma unroll
                    for (int si = 0; si < 6; si++)
#pragma unroll
                        for (int kx = 0; kx < 9; kx++)
                            acc[sj * 6 + si] = fmaf(rv[2 * si + kx], w[kx], acc[sj * 6 + si]);
                }
            }
        }
    }

    float bo = __ldg(pb + oc);
    float* outp = g_uraw + (size_t)b * 9216 + oc * 36;
#pragma unroll
    for (int s = 0; s < 36; s++) outp[s] = acc[s] + bo;
}

// ------------- squash u over groups of 8 -------------
__global__ void k_squash() {
    int idx = blockIdx.x * blockDim.x + threadIdx.x;   // B*1152
    if (idx >= NB * NR) return;
    const float4* p = (const float4*)(g_uraw + (size_t)idx * 8);
    float4 a = p[0], c = p[1];
    float sn = a.x*a.x + a.y*a.y + a.z*a.z + a.w*a.w +
               c.x*c.x + c.y*c.y + c.z*c.z + c.w*c.w;
    float f = sqrtf(sn) / (1.0f + sn);
    float4* o = (float4*)(g_u + (size_t)idx * 8);
    a.x*=f; a.y*=f; a.z*=f; a.w*=f; c.x*=f; c.y*=f; c.z*=f; c.w*=f;
    o[0] = a; o[1] = c;
}

// ------------- u_hat[b,r,c,o] = sum_i W[r,c,o,i]*u[b,r,i] -------------
__global__ void __launch_bounds__(160) k_uhat(const float* __restrict__ W) {
    __shared__ float sWT[1280];    // [i][t] transposed
    int r = blockIdx.x;
    int t = threadIdx.x;           // t = c*16+o, 0..159
    for (int j = t; j < 1280; j += 160)
        sWT[j] = W[(size_t)r * 1280 + (j % 160) * 8 + j / 160];
    __syncthreads();

    float w0 = sWT[0*160+t], w1 = sWT[1*160+t], w2 = sWT[2*160+t], w3 = sWT[3*160+t];
    float w4 = sWT[4*160+t], w5 = sWT[5*160+t], w6 = sWT[6*160+t], w7 = sWT[7*160+t];

#pragma unroll 4
    for (int b = 0; b < NB; b++) {
        const float4* up = (const float4*)(g_u + (size_t)b * 9216 + r * 8);
        float4 ua = up[0], ub = up[1];
        float acc = ua.x*w0 + ua.y*w1 + ua.z*w2 + ua.w*w3
                  + ub.x*w4 + ub.y*w5 + ub.z*w6 + ub.w*w7;
        g_uhat[((size_t)b * NR + r) * 160 + t] = acc;
    }
}

// ------------- softmax over routes (axis r) per class c -------------
__global__ void k_softmax() {
    __shared__ float sred[128];
    int c = blockIdx.x;
    int t = threadIdx.x;
    float mx = -1e30f;
    for (int r = t; r < NR; r += 128) mx = fmaxf(mx, g_bij[r * NC2 + c]);
    sred[t] = mx; __syncthreads();
    for (int st = 64; st >= 1; st >>= 1) { if (t < st) sred[t] = fmaxf(sred[t], sred[t + st]); __syncthreads(); }
    mx = sred[0]; __syncthreads();
    float sm = 0.f;
    for (int r = t; r < NR; r += 128) sm += expf(g_bij[r * NC2 + c] - mx);
    sred[t] = sm; __syncthreads();
    for (int st = 64; st >= 1; st >>= 1) { if (t < st) sred[t] += sred[t + st]; __syncthreads(); }
    float inv = 1.0f / sred[0];
    for (int r = t; r < NR; r += 128)
        g_cij[r * NC2 + c] = expf(g_bij[r * NC2 + c] - mx) * inv;
}

// ------------- s_j + squash -> v ; optionally write d_out -------------
__global__ void __launch_bounds__(256) k_sj(float* out) {
    __shared__ float sred[256];
    int b = blockIdx.x, c = blockIdx.y;
    int t = threadIdx.x;
    int o = t & 15, rg = t >> 4;
    float acc = 0.f;
    for (int r = rg; r < NR; r += 16) {
        float cij = __ldg(g_cij + r * NC2 + c);
        acc = fmaf(cij, g_uhat[(((size_t)b * NR + r) * NC2 + c) * 16 + o], acc);
    }
    sred[t] = acc; __syncthreads();
    for (int st = 8; st >= 1; st >>= 1) {
        if (rg < st) sred[t] += sred[t + st * 16];
        __syncthreads();
    }
    if (rg == 0) {
        float s = sred[o];
        float v = s * fabsf(s) / (1.0f + s * s);
        g_v[(b * NC2 + c) * 16 + o] = v;
        if (out) out[(b * NC2 + c) * 16 + o] = v;
    }
}

// ------------- a_ij = mean_b sum_o u_hat*v ; b_ij += a_ij -------------
__global__ void __launch_bounds__(128) k_aij() {
    __shared__ float sred[128];
    int r = blockIdx.x, c = blockIdx.y;
    int t = threadIdx.x;
    int o = t & 15, bg = t >> 4;
    float acc = 0.f;
    for (int b = bg; b < NB; b += 8)
        acc = fmaf(g_uhat[(((size_t)b * NR + r) * NC2 + c) * 16 + o],
                   __ldg(g_v + (b * NC2 + c) * 16 + o), acc);
    sred[t] = acc; __syncthreads();
    for (int st = 64; st >= 1; st >>= 1) { if (t < st) sred[t] += sred[t + st]; __syncthreads(); }
    if (t == 0) g_bij[r * NC2 + c] += sred[0] * (1.0f / NB);
}

// ------------- classifiers -------------
__global__ void __launch_bounds__(128) k_cls(const float* __restrict__ w1,
                                             const float* __restrict__ b1,
                                             const float* __restrict__ w2,
                                             const float* __restrict__ b2,
                                             float* out) {
    __shared__ float sfeat[160];
    __shared__ float sred[128];
    int b = blockIdx.x, k = blockIdx.y;
    int t = threadIdx.x;
    for (int j = t; j < 160; j += 128) sfeat[j] = g_v[b * 160 + j];
    __syncthreads();

    float val = 0.f;
    if (t < 100) {
        float acc = __ldg(b1 + k * 100 + t);
        const float* wp = w1 + (size_t)k * 16000 + t;
#pragma unroll 4
        for (int f = 0; f < 160; f++)
            acc = fmaf(sfeat[f], wp[f * 100], acc);
        acc = fmaxf(acc, 0.f);
        val = acc * __ldg(w2 + k * 100 + t);
    }
    sred[t] = val; __syncthreads();
    for (int st = 64; st >= 1; st >>= 1) { if (t < st) sred[t] += sred[t + st]; __syncthreads(); }
    if (t == 0) {
        float logit = sred[0] + __ldg(b2 + k);
        out[40960 + b * NC2 + k] = 1.0f / (1.0f + expf(-logit));
    }
}

extern "C" void kernel_launch(void* const* d_in, const int* in_sizes, int n_in,
                              void* d_out, int out_size) {
    const float* data    = (const float*)d_in[0];
    const float* conv1_w = (const float*)d_in[1];
    const float* conv1_b = (const float*)d_in[2];
    const float* conv2_w = (const float*)d_in[3];
    const float* conv2_b = (const float*)d_in[4];
    const float* prim_w  = (const float*)d_in[5];
    const float* prim_b  = (const float*)d_in[6];
    const float* W       = (const float*)d_in[7];
    const float* cls_w1  = (const float*)d_in[8];
    const float* cls_b1  = (const float*)d_in[9];
    const float* cls_w2  = (const float*)d_in[10];
    const float* cls_b2  = (const float*)d_in[11];
    float* out = (float*)d_out;

    k_zero<<<45, 256>>>();
    k_conv1pool<<<1444, 256>>>(data, conv1_w, conv1_b);
    k_conv2<<<dim3(10, NB), dim3(64, 4)>>>(conv2_w, conv2_b);
    k_pool2<<<(NB * 128 * 400) / 256, 256>>>();
    k_wT<<<10368, 256>>>(prim_w);
    k_prim<<<NB, 256>>>(prim_b);
    k_squash<<<(NB * NR + 255) / 256, 256>>>();
    k_uhat<<<NR, 160>>>(W);

    for (int it = 0; it < 3; it++) {
        k_softmax<<<NC2, 128>>>();
        k_sj<<<dim3(NB, NC2), 256>>>(it == 2 ? out : nullptr);
        if (it < 2) k_aij<<<dim3(NR, NC2), 128>>>();
    }
    k_cls<<<dim3(NB, NC2), 128>>>(cls_w1, cls_b1, cls_w2, cls_b2, out);
}

// round 3
// speedup vs baseline: 1.0337x; 1.0337x over previous
#include <cuda_runtime.h>
#include <math.h>

#define NB 256
#define NR 1152
#define NC2 10
#define NO 16
#define NI 8

typedef unsigned long long u64;

// ------------- packed f32x2 helpers -------------
__device__ __forceinline__ u64 fma2(u64 a, u64 b, u64 c) {
    u64 d;
    asm("fma.rn.f32x2 %0, %1, %2, %3;" : "=l"(d) : "l"(a), "l"(b), "l"(c));
    return d;
}
__device__ __forceinline__ u64 pk2(float v) {           // (v, v)
    u64 r;
    asm("mov.b64 %0, {%1, %1};" : "=l"(r) : "f"(v));
    return r;
}
__device__ __forceinline__ u64 f2pk(float lo, float hi) {
    return (u64)__float_as_uint(lo) | ((u64)__float_as_uint(hi) << 32);
}
__device__ __forceinline__ float f2lo(u64 v) { return __uint_as_float((unsigned)v); }
__device__ __forceinline__ float f2hi(u64 v) { return __uint_as_float((unsigned)(v >> 32)); }

// ------------- scratch (device globals) -------------
__device__ float g_pool1[(size_t)NB * 64 * 38 * 38];
__device__ float g_pool2[(size_t)NB * 128 * 20 * 20];
__device__ u64   g_wT2[(size_t)10368 * 128];           // packed (oc, oc+128) prim weights [k][t]
__device__ float g_uraw[(size_t)NB * 9216];
__device__ float g_u[(size_t)NB * 9216];
__device__ float g_uhat[(size_t)NB * NR * NC2 * NO];
__device__ float g_bij[NR * NC2];
__device__ float g_cij[NR * NC2];
__device__ float g_v[NB * NC2 * NO];

// ------------- zero b_ij -------------
__global__ void k_zero() {
    int i = blockIdx.x * blockDim.x + threadIdx.x;
    if (i < NR * NC2) g_bij[i] = 0.f;
}

// ------------- conv1(3->64,3x3,valid)+ReLU+maxpool(2,2,pad1) -------------
__global__ void __launch_bounds__(256) k_conv1pool(const float* __restrict__ data,
                                                   const float* __restrict__ w1,
                                                   const float* __restrict__ b1) {
    int idx = blockIdx.x * blockDim.x + threadIdx.x;   // B*1444 threads
    int p = idx % 1444;
    int b = idx / 1444;
    int pj = p / 38, pi = p % 38;
    int y0 = 2 * pj - 1, x0 = 2 * pi - 1;

    float iv[3][4][4];
#pragma unroll
    for (int ic = 0; ic < 3; ic++)
#pragma unroll
        for (int dy = 0; dy < 4; dy++) {
            int yy = y0 + dy;
#pragma unroll
            for (int dx = 0; dx < 4; dx++) {
                int xx = x0 + dx;
                float v = 0.f;
                if (yy >= 0 && yy < 76 && xx >= 0 && xx < 76)
                    v = data[((size_t)(b * 3 + ic) * 76 + yy) * 76 + xx];
                iv[ic][dy][dx] = v;
            }
        }

    bool rv0 = (y0 >= 0), rv1 = (y0 + 1 <= 73);
    bool cv0 = (x0 >= 0), cv1 = (x0 + 1 <= 73);
    size_t obase = (size_t)b * 64 * 1444 + (size_t)pj * 38 + pi;

#pragma unroll 1
    for (int oc = 0; oc < 64; oc++) {
        const float* wp = w1 + oc * 27;
        float s00 = 0.f, s01 = 0.f, s10 = 0.f, s11 = 0.f;
#pragma unroll
        for (int k = 0; k < 27; k++) {
            int ic = k / 9, r = (k / 3) % 3, c2 = k % 3;
            float w = __ldg(wp + k);
            s00 = fmaf(iv[ic][r][c2],         w, s00);
            s01 = fmaf(iv[ic][r][c2 + 1],     w, s01);
            s10 = fmaf(iv[ic][r + 1][c2],     w, s10);
            s11 = fmaf(iv[ic][r + 1][c2 + 1], w, s11);
        }
        float bo = __ldg(b1 + oc);
        float m = 0.f;
        if (rv0 && cv0) m = fmaxf(m, s00 + bo);
        if (rv0 && cv1) m = fmaxf(m, s01 + bo);
        if (rv1 && cv0) m = fmaxf(m, s10 + bo);
        if (rv1 && cv1) m = fmaxf(m, s11 + bo);
        g_pool1[obase + (size_t)oc * 1444] = m;
    }
}

// ------------- conv2(64->128,3x3,pad1)+ReLU+maxpool(2,2,pad1), f32x2 -------------
// block (64,4): tx = oc pair (tx, tx+64), ty = conv row r0+ty with r0 = 4*bx-1.
// Each block produces pool rows p0=2*bx, p0+1 for all 128 oc of one image.
__global__ void __launch_bounds__(256) k_conv2pool(const float* __restrict__ w2,
                                                   const float* __restrict__ b2) {
    __shared__ __align__(16) float sm[11136];          // 44.5 KB
    float* s_in = sm;                                  // 8*6*40 = 1920 floats
    u64*   s_w2 = (u64*)(sm + 1920);                   // 72*64 packed weights

    int b = blockIdx.y;
    int r0 = (int)blockIdx.x * 4 - 1;
    int tx = threadIdx.x;
    int ty = threadIdx.y;
    int tid = ty * 64 + tx;
    int row = r0 + ty;
    bool rowok = (row >= 0 && row < 38);

    u64 acc2[38];
#pragma unroll
    for (int x = 0; x < 38; x++) acc2[x] = 0ull;

#pragma unroll 1
    for (int ic0 = 0; ic0 < 64; ic0 += 8) {
        __syncthreads();
        for (int i = tid; i < 1920; i += 256) {
            int ic = i / 240, rem = i % 240;
            int rr = rem / 40, cc = rem % 40;
            int gr = r0 - 1 + rr, gc = cc - 1;
            float vv = 0.f;
            if (gr >= 0 && gr < 38 && gc >= 0 && gc < 38)
                vv = g_pool1[(((size_t)b * 64 + ic0 + ic) * 38 + gr) * 38 + gc];
            s_in[i] = vv;
        }
        for (int i = tid; i < 4608; i += 256) {
            int k = i >> 6, j = i & 63;
            s_w2[i] = f2pk(w2[(size_t)j * 576 + ic0 * 9 + k],
                           w2[(size_t)(j + 64) * 576 + ic0 * 9 + k]);
        }
        __syncthreads();

        if (rowok) {
#pragma unroll 1
            for (int icl = 0; icl < 8; icl++) {
#pragma unroll
                for (int ky = 0; ky < 3; ky++) {
                    const float* irow = s_in + icl * 240 + (ty + ky) * 40;
                    const u64* wr = s_w2 + (icl * 9 + ky * 3) * 64;
                    u64 w0 = wr[tx], w1 = wr[64 + tx], w2p = wr[128 + tx];
                    u64 pv0 = pk2(irow[0]), pv1 = pk2(irow[1]);
#pragma unroll
                    for (int x = 0; x < 38; x++) {
                        u64 pv2 = pk2(irow[x + 2]);
                        acc2[x] = fma2(pv2, w2p, fma2(pv1, w1, fma2(pv0, w0, acc2[x])));
                        pv0 = pv1; pv1 = pv2;
                    }
                }
            }
        }
    }

    // ---- fused maxpool (2,2,pad1): stage relu'd rows in smem, pool, store ----
    float bA = __ldg(b2 + tx), bB = __ldg(b2 + tx + 64);
    float* s_pool = sm;                                // 4*38*64 = 9728 floats
    int p0 = (int)blockIdx.x * 2;

#pragma unroll 1
    for (int half = 0; half < 2; half++) {
        __syncthreads();
        float bb = half ? bB : bA;
#pragma unroll
        for (int x = 0; x < 38; x++) {
            float v = half ? f2hi(acc2[x]) : f2lo(acc2[x]);
            s_pool[(ty * 38 + x) * 64 + tx] = rowok ? fmaxf(v + bb, 0.f) : 0.f;
        }
        __syncthreads();
        for (int j = tid; j < 2560; j += 256) {
            int pi = j % 20;
            int pr = (j / 20) & 1;
            int oc = j / 40;
            int x0 = 2 * pi - 1;
            int tA = 2 * pr, tB = 2 * pr + 1;          // local conv rows for pool row p0+pr
            float m = 0.f;
            if (x0 >= 0)
                m = fmaxf(m, fmaxf(s_pool[(tA * 38 + x0) * 64 + oc],
                                   s_pool[(tB * 38 + x0) * 64 + oc]));
            if (x0 + 1 <= 37)
                m = fmaxf(m, fmaxf(s_pool[(tA * 38 + x0 + 1) * 64 + oc],
                                   s_pool[(tB * 38 + x0 + 1) * 64 + oc]));
            g_pool2[((size_t)(b * 128 + oc + half * 64) * 20 + p0 + pr) * 20 + pi] = m;
        }
    }
}

// ------------- pack prim weights: (oc, oc+128) pairs, [k][t] -------------
__global__ void k_wT2(const float* __restrict__ pw) {
    int i = blockIdx.x * blockDim.x + threadIdx.x;     // 10368*128 threads
    int k = i >> 7, t = i & 127;
    g_wT2[i] = f2pk(pw[(size_t)t * 10368 + k], pw[(size_t)(t + 128) * 10368 + k]);
}

// ------------- PrimaryCaps conv (128->256, 9x9, s2, 6x6 out), f32x2 -------------
// grid (B, 2): blockIdx.y selects sj rows [3*y, 3*y+2]. 128 threads, 2 oc each.
__global__ void __launch_bounds__(128) k_prim(const float* __restrict__ pb) {
    __shared__ float s_in[16 * 260];                   // 16 ic x 13 rows x 20 cols
    int b = blockIdx.x;
    int sj0 = blockIdx.y * 3;
    int t = threadIdx.x;

    u64 acc2[18];
#pragma unroll
    for (int s = 0; s < 18; s++) acc2[s] = 0ull;

#pragma unroll 1
    for (int ic0 = 0; ic0 < 128; ic0 += 16) {
        __syncthreads();
        for (int i = t; i < 4160; i += 128) {
            int ic = i / 260, rem = i % 260;
            int rr = rem / 20, cc = rem % 20;
            s_in[i] = g_pool2[((size_t)(b * 128 + ic0 + ic) * 20 + 2 * sj0 + rr) * 20 + cc];
        }
        __syncthreads();

#pragma unroll 1
        for (int icl = 0; icl < 16; icl++) {
#pragma unroll 1
            for (int ky = 0; ky < 9; ky++) {
                const u64* wp = g_wT2 + ((size_t)(ic0 + icl) * 81 + ky * 9) * 128 + t;
                u64 w[9];
#pragma unroll
                for (int kx = 0; kx < 9; kx++) w[kx] = wp[(size_t)kx * 128];
#pragma unroll
                for (int sl = 0; sl < 3; sl++) {
                    const float* rp = s_in + icl * 260 + (2 * sl + ky) * 20;
                    u64 pv[19];
#pragma unroll
                    for (int x = 0; x < 19; x++) pv[x] = pk2(rp[x]);
#pragma unroll
                    for (int si = 0; si < 6; si++)
#pragma unroll
                        for (int kx = 0; kx < 9; kx++)
                            acc2[sl * 6 + si] = fma2(pv[2 * si + kx], w[kx], acc2[sl * 6 + si]);
                }
            }
        }
    }

    float b0 = __ldg(pb + t), b1 = __ldg(pb + t + 128);
    float* o0 = g_uraw + (size_t)b * 9216 + t * 36 + sj0 * 6;
    float* o1 = g_uraw + (size_t)b * 9216 + (t + 128) * 36 + sj0 * 6;
#pragma unroll
    for (int j = 0; j < 18; j++) {
        o0[j] = f2lo(acc2[j]) + b0;
        o1[j] = f2hi(acc2[j]) + b1;
    }
}

// ------------- squash u over groups of 8 -------------
__global__ void k_squash() {
    int idx = blockIdx.x * blockDim.x + threadIdx.x;
    if (idx >= NB * NR) return;
    const float4* p = (const float4*)(g_uraw + (size_t)idx * 8);
    float4 a = p[0], c = p[1];
    float sn = a.x*a.x + a.y*a.y + a.z*a.z + a.w*a.w +
               c.x*c.x + c.y*c.y + c.z*c.z + c.w*c.w;
    float f = sqrtf(sn) / (1.0f + sn);
    float4* o = (float4*)(g_u + (size_t)idx * 8);
    a.x*=f; a.y*=f; a.z*=f; a.w*=f; c.x*=f; c.y*=f; c.z*=f; c.w*=f;
    o[0] = a; o[1] = c;
}

// ------------- u_hat[b,r,c,o] = sum_i W[r,c,o,i]*u[b,r,i] -------------
__global__ void __launch_bounds__(160) k_uhat(const float* __restrict__ W) {
    __shared__ float sWT[1280];
    int r = blockIdx.x;
    int t = threadIdx.x;
    for (int j = t; j < 1280; j += 160)
        sWT[j] = W[(size_t)r * 1280 + (j % 160) * 8 + j / 160];
    __syncthreads();

    float w0 = sWT[0*160+t], w1 = sWT[1*160+t], w2 = sWT[2*160+t], w3 = sWT[3*160+t];
    float w4 = sWT[4*160+t], w5 = sWT[5*160+t], w6 = sWT[6*160+t], w7 = sWT[7*160+t];

#pragma unroll 4
    for (int b = 0; b < NB; b++) {
        const float4* up = (const float4*)(g_u + (size_t)b * 9216 + r * 8);
        float4 ua = up[0], ub = up[1];
        float acc = ua.x*w0 + ua.y*w1 + ua.z*w2 + ua.w*w3
                  + ub.x*w4 + ub.y*w5 + ub.z*w6 + ub.w*w7;
        g_uhat[((size_t)b * NR + r) * 160 + t] = acc;
    }
}

// ------------- softmax over routes per class -------------
__global__ void k_softmax() {
    __shared__ float sred[128];
    int c = blockIdx.x;
    int t = threadIdx.x;
    float mx = -1e30f;
    for (int r = t; r < NR; r += 128) mx = fmaxf(mx, g_bij[r * NC2 + c]);
    sred[t] = mx; __syncthreads();
    for (int st = 64; st >= 1; st >>= 1) { if (t < st) sred[t] = fmaxf(sred[t], sred[t + st]); __syncthreads(); }
    mx = sred[0]; __syncthreads();
    float sm = 0.f;
    for (int r = t; r < NR; r += 128) sm += expf(g_bij[r * NC2 + c] - mx);
    sred[t] = sm; __syncthreads();
    for (int st = 64; st >= 1; st >>= 1) { if (t < st) sred[t] += sred[t + st]; __syncthreads(); }
    float inv = 1.0f / sred[0];
    for (int r = t; r < NR; r += 128)
        g_cij[r * NC2 + c] = expf(g_bij[r * NC2 + c] - mx) * inv;
}

// ------------- s_j + squash -> v -------------
__global__ void __launch_bounds__(256) k_sj(float* out) {
    __shared__ float sred[256];
    int b = blockIdx.x, c = blockIdx.y;
    int t = threadIdx.x;
    int o = t & 15, rg = t >> 4;
    float acc = 0.f;
    for (int r = rg; r < NR; r += 16) {
        float cij = __ldg(g_cij + r * NC2 + c);
        acc = fmaf(cij, g_uhat[(((size_t)b * NR + r) * NC2 + c) * 16 + o], acc);
    }
    sred[t] = acc; __syncthreads();
    for (int st = 8; st >= 1; st >>= 1) {
        if (rg < st) sred[t] += sred[t + st * 16];
        __syncthreads();
    }
    if (rg == 0) {
        float s = sred[o];
        float v = s * fabsf(s) / (1.0f + s * s);
        g_v[(b * NC2 + c) * 16 + o] = v;
        if (out) out[(b * NC2 + c) * 16 + o] = v;
    }
}

// ------------- a_ij accumulate into b_ij -------------
__global__ void __launch_bounds__(128) k_aij() {
    __shared__ float sred[128];
    int r = blockIdx.x, c = blockIdx.y;
    int t = threadIdx.x;
    int o = t & 15, bg = t >> 4;
    float acc = 0.f;
    for (int b = bg; b < NB; b += 8)
        acc = fmaf(g_uhat[(((size_t)b * NR + r) * NC2 + c) * 16 + o],
                   __ldg(g_v + (b * NC2 + c) * 16 + o), acc);
    sred[t] = acc; __syncthreads();
    for (int st = 64; st >= 1; st >>= 1) { if (t < st) sred[t] += sred[t + st]; __syncthreads(); }
    if (t == 0) g_bij[r * NC2 + c] += sred[0] * (1.0f / NB);
}

// ------------- classifiers -------------
__global__ void __launch_bounds__(128) k_cls(const float* __restrict__ w1,
                                             const float* __restrict__ b1,
                                             const float* __restrict__ w2,
                                             const float* __restrict__ b2,
                                             float* out) {
    __shared__ float sfeat[160];
    __shared__ float sred[128];
    int b = blockIdx.x, k = blockIdx.y;
    int t = threadIdx.x;
    for (int j = t; j < 160; j += 128) sfeat[j] = g_v[b * 160 + j];
    __syncthreads();

    float val = 0.f;
    if (t < 100) {
        float acc = __ldg(b1 + k * 100 + t);
        const float* wp = w1 + (size_t)k * 16000 + t;
#pragma unroll 4
        for (int f = 0; f < 160; f++)
            acc = fmaf(sfeat[f], wp[f * 100], acc);
        acc = fmaxf(acc, 0.f);
        val = acc * __ldg(w2 + k * 100 + t);
    }
    sred[t] = val; __syncthreads();
    for (int st = 64; st >= 1; st >>= 1) { if (t < st) sred[t] += sred[t + st]; __syncthreads(); }
    if (t == 0) {
        float logit = sred[0] + __ldg(b2 + k);
        out[40960 + b * NC2 + k] = 1.0f / (1.0f + expf(-logit));
    }
}

extern "C" void kernel_launch(void* const* d_in, const int* in_sizes, int n_in,
                              void* d_out, int out_size) {
    const float* data    = (const float*)d_in[0];
    const float* conv1_w = (const float*)d_in[1];
    const float* conv1_b = (const float*)d_in[2];
    const float* conv2_w = (const float*)d_in[3];
    const float* conv2_b = (const float*)d_in[4];
    const float* prim_w  = (const float*)d_in[5];
    const float* prim_b  = (const float*)d_in[6];
    const float* W       = (const float*)d_in[7];
    const float* cls_w1  = (const float*)d_in[8];
    const float* cls_b1  = (const float*)d_in[9];
    const float* cls_w2  = (const float*)d_in[10];
    const float* cls_b2  = (const float*)d_in[11];
    float* out = (float*)d_out;

    k_zero<<<45, 256>>>();
    k_conv1pool<<<1444, 256>>>(data, conv1_w, conv1_b);
    k_conv2pool<<<dim3(10, NB), dim3(64, 4)>>>(conv2_w, conv2_b);
    k_wT2<<<5184, 256>>>(prim_w);
    k_prim<<<dim3(NB, 2), 128>>>(prim_b);
    k_squash<<<(NB * NR + 255) / 256, 256>>>();
    k_uhat<<<NR, 160>>>(W);

    for (int it = 0; it < 3; it++) {
        k_softmax<<<NC2, 128>>>();
        k_sj<<<dim3(NB, NC2), 256>>>(it == 2 ? out : nullptr);
        if (it < 2) k_aij<<<dim3(NR, NC2), 128>>>();
    }
    k_cls<<<dim3(NB, NC2), 128>>>(cls_w1, cls_b1, cls_w2, cls_b2, out);
}